// round 14
// baseline (speedup 1.0000x reference)
#include <cuda_runtime.h>
#include <cuda_fp16.h>
#include <cstdint>

#define BDIM   64
#define IOD    8192
#define OTILE  32
#define KC     128
#define KSPLIT 2
#define KHALF  (IOD / KSPLIT)      // 4096
#define NITER  (KHALF / KC)        // 32
#define NTILES (IOD / OTILE)       // 256
// per-warp quadrant: 2 stages x (16 rows x 128B fp16) = 4KB; 4 warps -> 16KB
#define QSTAGE 2048

// scratch (no cudaMalloc allowed)
// x packed as m16n8k16 A-fragments (fp16): index = (ks16*4 + mtile)*32 + lane
__device__ uint4 g_xf[(IOD / 16) * 4 * 32];      // 1 MB
__device__ float g_part[KSPLIT][BDIM * IOD];     // split-K partials (alpha applied)
__device__ unsigned int g_cnt[NTILES];           // per-otile completion counters

// ---------------- prep: x -> fp16 A-fragment layout ----------------
__global__ void prep_x(const float* __restrict__ x) {
    int t = blockIdx.x * blockDim.x + threadIdx.x;   // (ks, mt, lane)
    if (t >= (IOD / 16) * 4 * 32) return;
    int lane = t & 31;
    int mt   = (t >> 5) & 3;
    int ks   = t >> 7;
    int b0 = mt * 16 + (lane >> 2);
    int k0 = ks * 16 + (lane & 3) * 2;
    const float* p = x + (size_t)b0 * IOD + k0;
    float2 v00 = *reinterpret_cast<const float2*>(p);               // (r,   c)
    float2 v10 = *reinterpret_cast<const float2*>(p + 8 * IOD);     // (r+8, c)
    float2 v01 = *reinterpret_cast<const float2*>(p + 8);           // (r,   c+8)
    float2 v11 = *reinterpret_cast<const float2*>(p + 8 * IOD + 8); // (r+8, c+8)
    uint4 f;
    __half2 h;
    h = __floats2half2_rn(v00.x, v00.y); f.x = *reinterpret_cast<uint32_t*>(&h);
    h = __floats2half2_rn(v10.x, v10.y); f.y = *reinterpret_cast<uint32_t*>(&h);
    h = __floats2half2_rn(v01.x, v01.y); f.z = *reinterpret_cast<uint32_t*>(&h);
    h = __floats2half2_rn(v11.x, v11.y); f.w = *reinterpret_cast<uint32_t*>(&h);
    g_xf[t] = f;
}

// ---------------- helpers ----------------
__device__ __forceinline__ uint32_t swz(uint32_t off) {   // SW128 Swizzle<3,4,3>
    return off ^ ((off >> 3) & 0x70);
}

__device__ __forceinline__ void ldm_x4(uint32_t& r0, uint32_t& r1,
                                       uint32_t& r2, uint32_t& r3, uint32_t addr) {
    asm volatile("ldmatrix.sync.aligned.m8n8.x4.shared.b16 {%0,%1,%2,%3}, [%4];"
                 : "=r"(r0), "=r"(r1), "=r"(r2), "=r"(r3) : "r"(addr));
}

__device__ __forceinline__ void mma_f16(float* c, const uint4& a,
                                        uint32_t b0, uint32_t b1) {
    asm volatile("mma.sync.aligned.m16n8k16.row.col.f32.f16.f16.f32 "
                 "{%0,%1,%2,%3}, {%4,%5,%6,%7}, {%8,%9}, {%0,%1,%2,%3};"
                 : "+f"(c[0]), "+f"(c[1]), "+f"(c[2]), "+f"(c[3])
                 : "r"(a.x), "r"(a.y), "r"(a.z), "r"(a.w), "r"(b0), "r"(b1));
}

// ternary quantize one fp32 -> fp16 {-1, 0, +1} bit pattern
__device__ __forceinline__ uint32_t quant1(float f, float thr) {
    uint32_t u = __float_as_uint(f);
    return (fabsf(f) > thr) ? (0x3C00u | ((u >> 16) & 0x8000u)) : 0u;
}

// W loader: warp-private; thread owns 32 consecutive fp32 of its row
__device__ __forceinline__ void load_w(const float* __restrict__ wp,
                                       uint4 wreg[8]) {
#pragma unroll
    for (int p = 0; p < 8; ++p)
        wreg[p] = *reinterpret_cast<const uint4*>(wp + p * 4);
}

// store to the warp's private quadrant stage
__device__ __forceinline__ void store_w(uint32_t qstg, int lrow2, int lcol2,
                                        float thr, const uint4 wreg[8]) {
#pragma unroll
    for (int p = 0; p < 8; p += 2) {
        const uint4& u0 = wreg[p];
        const uint4& u1 = wreg[p + 1];
        uint32_t q0 = quant1(__uint_as_float(u0.x), thr);
        uint32_t q1 = quant1(__uint_as_float(u0.y), thr);
        uint32_t q2 = quant1(__uint_as_float(u0.z), thr);
        uint32_t q3 = quant1(__uint_as_float(u0.w), thr);
        uint32_t q4 = quant1(__uint_as_float(u1.x), thr);
        uint32_t q5 = quant1(__uint_as_float(u1.y), thr);
        uint32_t q6 = quant1(__uint_as_float(u1.z), thr);
        uint32_t q7 = quant1(__uint_as_float(u1.w), thr);
        uint4 v;
        v.x = q0 | (q1 << 16);
        v.y = q2 | (q3 << 16);
        v.z = q4 | (q5 << 16);
        v.w = q6 | (q7 << 16);
        asm volatile("st.shared.v4.b32 [%0], {%1,%2,%3,%4};"
                     :: "r"(qstg + swz((uint32_t)(lrow2 * 128 + lcol2 * 64 + p * 8))),
                        "r"(v.x), "r"(v.y), "r"(v.z), "r"(v.w));
    }
}

// one 128-k stage for one warp: private quadrant holds its (k-half, n16) slice
__device__ __forceinline__ void mma_stage(uint32_t qstg, int ksg_it, int kw, int lane,
                                          float acc[4][2][4]) {
    const int lrow = lane & 15;
    const uint32_t lk16 = (uint32_t)((lane >> 4) * 16);

#pragma unroll
    for (int ks = 0; ks < 4; ++ks) {
        uint32_t b0, b1, b2, b3;
        ldm_x4(b0, b1, b2, b3,
               qstg + swz((uint32_t)(lrow * 128 + ks * 32) + lk16));
        const int ksg = ksg_it + kw * 4 + ks;
#pragma unroll
        for (int mt = 0; mt < 4; ++mt) {
            uint4 a = g_xf[(size_t)(ksg * 4 + mt) * 32 + lane];
            mma_f16(acc[mt][0], a, b0, b2);
            mma_f16(acc[mt][1], a, b1, b3);
        }
    }
}

__global__ __launch_bounds__(128, 4) void qlin(
    const float* __restrict__ wgt,
    const float* __restrict__ alpha,
    const float* __restrict__ bias,
    float* __restrict__ out)
{
    __shared__ __align__(1024) unsigned char smem[4 * 2 * QSTAGE];  // 16KB
    __shared__ unsigned int s_last;

    const int otile  = blockIdx.x & (NTILES - 1);
    const int khalf  = blockIdx.x >> 8;
    const int n0     = otile * OTILE;
    const int k0     = khalf * KHALF;

    const int tid  = threadIdx.x;
    const int lane = tid & 31;
    const int warp = tid >> 5;
    const int kw = warp >> 1;          // k-half within stage
    const int nw = warp & 1;           // n-half (O)
    const int nb = nw * 16;            // warp's local n base

    const uint32_t smem_base = (uint32_t)__cvta_generic_to_shared(smem);
    const uint32_t qbase = smem_base + (uint32_t)(warp * 2 * QSTAGE);

    // warp-private W loader: 2 threads per row (16 rows), 32 consecutive fp32 each
    const int lrow2 = lane >> 1;
    const int lcol2 = lane & 1;
    const int wr_g  = n0 + nb + lrow2;
    const float thr = 0.5f * (alpha[wr_g] + 1e-8f);
    const float* wp0 = wgt + (size_t)wr_g * IOD + k0 + kw * 64 + lcol2 * 32;

    float acc[4][2][4];
#pragma unroll
    for (int i = 0; i < 4; ++i)
#pragma unroll
        for (int j = 0; j < 2; ++j)
#pragma unroll
            for (int k = 0; k < 4; ++k) acc[i][j][k] = 0.0f;

    uint4 wreg[8];

    // prologue: fill own stage 0
    load_w(wp0, wreg);
    store_w(qbase, lrow2, lcol2, thr, wreg);
    __syncwarp();

    const int ksg0 = k0 / 16;
    for (int it = 0; it < NITER; ++it) {
        const uint32_t cur = (uint32_t)(it & 1);
        if (it + 1 < NITER)
            load_w(wp0 + (it + 1) * KC, wreg);

        mma_stage(qbase + cur * QSTAGE, ksg0 + it * 8, kw, lane, acc);

        if (it + 1 < NITER)
            store_w(qbase + (cur ^ 1u) * QSTAGE, lrow2, lcol2, thr, wreg);
        __syncwarp();
    }

    // ---- cross-k reduce: kw=1 warps dump acc to smem, kw=0 warps add ----
    __syncthreads();
    float4* rbuf = reinterpret_cast<float4*>(smem);   // 8KB, aliases stages
    if (kw == 1) {
#pragma unroll
        for (int mt = 0; mt < 4; ++mt)
#pragma unroll
            for (int nt = 0; nt < 2; ++nt) {
                int r = mt * 2 + nt;
                rbuf[(nw * 8 + r) * 32 + lane] =
                    make_float4(acc[mt][nt][0], acc[mt][nt][1],
                                acc[mt][nt][2], acc[mt][nt][3]);
            }
    }
    __syncthreads();
    if (kw == 0) {
#pragma unroll
        for (int mt = 0; mt < 4; ++mt)
#pragma unroll
            for (int nt = 0; nt < 2; ++nt) {
                int r = mt * 2 + nt;
                float4 v = rbuf[(nw * 8 + r) * 32 + lane];
                acc[mt][nt][0] += v.x;
                acc[mt][nt][1] += v.y;
                acc[mt][nt][2] += v.z;
                acc[mt][nt][3] += v.w;
            }

        // scale by alpha in regs, write partial
        float* part = g_part[khalf];
#pragma unroll
        for (int mt = 0; mt < 4; ++mt) {
#pragma unroll
            for (int nt = 0; nt < 2; ++nt) {
                int brow = mt * 16 + (lane >> 2);
                int o0   = n0 + nb + nt * 8 + (lane & 3) * 2;
                float2 a2 = *reinterpret_cast<const float2*>(alpha + o0);
                acc[mt][nt][0] *= a2.x;
                acc[mt][nt][1] *= a2.y;
                acc[mt][nt][2] *= a2.x;
                acc[mt][nt][3] *= a2.y;
                float2 v0 = make_float2(acc[mt][nt][0], acc[mt][nt][1]);
                float2 v1 = make_float2(acc[mt][nt][2], acc[mt][nt][3]);
                *reinterpret_cast<float2*>(part + (size_t)brow * IOD + o0)       = v0;
                *reinterpret_cast<float2*>(part + (size_t)(brow + 8) * IOD + o0) = v1;
            }
        }
    }

    __threadfence();
    __syncthreads();
    if (tid == 0) {
        unsigned int old = atomicAdd(&g_cnt[otile], 1u);
        s_last = (((old + 1) % KSPLIT) == 0) ? 1u : 0u;
    }
    __syncthreads();

    if (s_last && kw == 0) {
        // this CTA finished second: its alpha*acc is in regs; add the other half + bias
        const float* other = g_part[khalf ^ 1];
#pragma unroll
        for (int mt = 0; mt < 4; ++mt) {
#pragma unroll
            for (int nt = 0; nt < 2; ++nt) {
                int brow = mt * 16 + (lane >> 2);
                int o0   = n0 + nb + nt * 8 + (lane & 3) * 2;
                float2 bi = *reinterpret_cast<const float2*>(bias + o0);
                float2 p0 = *reinterpret_cast<const float2*>(other + (size_t)brow * IOD + o0);
                float2 p1 = *reinterpret_cast<const float2*>(other + (size_t)(brow + 8) * IOD + o0);
                float2 v0, v1;
                v0.x = acc[mt][nt][0] + p0.x + bi.x;
                v0.y = acc[mt][nt][1] + p0.y + bi.y;
                v1.x = acc[mt][nt][2] + p1.x + bi.x;
                v1.y = acc[mt][nt][3] + p1.y + bi.y;
                *reinterpret_cast<float2*>(out + (size_t)brow * IOD + o0)       = v0;
                *reinterpret_cast<float2*>(out + (size_t)(brow + 8) * IOD + o0) = v1;
            }
        }
    }
}

extern "C" void kernel_launch(void* const* d_in, const int* in_sizes, int n_in,
                              void* d_out, int out_size) {
    const float* x     = (const float*)d_in[0];
    const float* wgt   = (const float*)d_in[1];
    const float* alpha = (const float*)d_in[2];
    const float* bias  = (const float*)d_in[3];
    float* out = (float*)d_out;

    prep_x<<<((IOD / 16) * 4 * 32 + 255) / 256, 256>>>(x);
    qlin<<<NTILES * KSPLIT, 128>>>(wgt, alpha, bias, out);
}

// round 15
// speedup vs baseline: 1.6894x; 1.6894x over previous
#include <cuda_runtime.h>
#include <cuda_fp16.h>
#include <cstdint>

#define BDIM   64
#define IOD    8192
#define OTILE  32
#define KC     128
#define KSPLIT 2
#define KHALF  (IOD / KSPLIT)      // 4096
#define NITER  (KHALF / KC)        // 32
#define STAGE_BYTES 8192           // W: 2 halves x (32 rows x 128B) fp16 ternary
#define NTILES (IOD / OTILE)       // 256

// scratch (no cudaMalloc allowed)
// x packed as m16n8k16 A-fragments (fp16): index = (ks16*4 + mtile)*32 + lane
__device__ uint4 g_xf[(IOD / 16) * 4 * 32];      // 1 MB
__device__ float g_part[KSPLIT][BDIM * IOD];     // split-K partials (alpha applied)
__device__ unsigned int g_cnt[NTILES];           // per-otile completion counters

// ---------------- prep: x -> fp16 A-fragment layout ----------------
__global__ void prep_x(const float* __restrict__ x) {
    int t = blockIdx.x * blockDim.x + threadIdx.x;   // (ks, mt, lane)
    if (t >= (IOD / 16) * 4 * 32) return;
    int lane = t & 31;
    int mt   = (t >> 5) & 3;
    int ks   = t >> 7;
    int b0 = mt * 16 + (lane >> 2);
    int k0 = ks * 16 + (lane & 3) * 2;
    const float* p = x + (size_t)b0 * IOD + k0;
    float2 v00 = *reinterpret_cast<const float2*>(p);               // (r,   c)
    float2 v10 = *reinterpret_cast<const float2*>(p + 8 * IOD);     // (r+8, c)
    float2 v01 = *reinterpret_cast<const float2*>(p + 8);           // (r,   c+8)
    float2 v11 = *reinterpret_cast<const float2*>(p + 8 * IOD + 8); // (r+8, c+8)
    uint4 f;
    __half2 h;
    h = __floats2half2_rn(v00.x, v00.y); f.x = *reinterpret_cast<uint32_t*>(&h);
    h = __floats2half2_rn(v10.x, v10.y); f.y = *reinterpret_cast<uint32_t*>(&h);
    h = __floats2half2_rn(v01.x, v01.y); f.z = *reinterpret_cast<uint32_t*>(&h);
    h = __floats2half2_rn(v11.x, v11.y); f.w = *reinterpret_cast<uint32_t*>(&h);
    g_xf[t] = f;
}

// ---------------- helpers ----------------
__device__ __forceinline__ uint32_t swz(uint32_t off) {   // SW128 Swizzle<3,4,3>
    return off ^ ((off >> 3) & 0x70);
}

__device__ __forceinline__ void ldm_x4(uint32_t& r0, uint32_t& r1,
                                       uint32_t& r2, uint32_t& r3, uint32_t addr) {
    asm volatile("ldmatrix.sync.aligned.m8n8.x4.shared.b16 {%0,%1,%2,%3}, [%4];"
                 : "=r"(r0), "=r"(r1), "=r"(r2), "=r"(r3) : "r"(addr));
}

__device__ __forceinline__ void mma_f16(float* c, const uint4& a,
                                        uint32_t b0, uint32_t b1) {
    asm volatile("mma.sync.aligned.m16n8k16.row.col.f32.f16.f16.f32 "
                 "{%0,%1,%2,%3}, {%4,%5,%6,%7}, {%8,%9}, {%0,%1,%2,%3};"
                 : "+f"(c[0]), "+f"(c[1]), "+f"(c[2]), "+f"(c[3])
                 : "r"(a.x), "r"(a.y), "r"(a.z), "r"(a.w), "r"(b0), "r"(b1));
}

// ternary quantize one fp32 -> fp16 {-1, 0, +1} bit pattern
__device__ __forceinline__ uint32_t quant1(float f, float thr) {
    uint32_t u = __float_as_uint(f);
    return (fabsf(f) > thr) ? (0x3C00u | ((u >> 16) & 0x8000u)) : 0u;
}

// W loader: 4 threads per row (32 rows); thread owns floats wc*8 + p*32 + [0,8)
__device__ __forceinline__ void load_w(const float* __restrict__ wp,
                                       uint4 wreg[8]) {
#pragma unroll
    for (int p = 0; p < 4; ++p) {
        wreg[2 * p]     = *reinterpret_cast<const uint4*>(wp + p * 32);
        wreg[2 * p + 1] = *reinterpret_cast<const uint4*>(wp + p * 32 + 4);
    }
}

__device__ __forceinline__ void store_w(uint32_t sbase, int stage,
                                        int wr, int wc, float thr,
                                        const uint4 wreg[8]) {
    const uint32_t base = sbase + (uint32_t)(stage * STAGE_BYTES);
#pragma unroll
    for (int p = 0; p < 4; ++p) {
        const uint4& u0 = wreg[2 * p];
        const uint4& u1 = wreg[2 * p + 1];
        uint32_t q0 = quant1(__uint_as_float(u0.x), thr);
        uint32_t q1 = quant1(__uint_as_float(u0.y), thr);
        uint32_t q2 = quant1(__uint_as_float(u0.z), thr);
        uint32_t q3 = quant1(__uint_as_float(u0.w), thr);
        uint32_t q4 = quant1(__uint_as_float(u1.x), thr);
        uint32_t q5 = quant1(__uint_as_float(u1.y), thr);
        uint32_t q6 = quant1(__uint_as_float(u1.z), thr);
        uint32_t q7 = quant1(__uint_as_float(u1.w), thr);
        uint4 v;
        v.x = q0 | (q1 << 16);
        v.y = q2 | (q3 << 16);
        v.z = q4 | (q5 << 16);
        v.w = q6 | (q7 << 16);
        // k = wc*8 + p*32: half = p>>1, byte-in-half = wc*16 + (p&1)*64
        uint32_t addr = base + (uint32_t)((p >> 1) * 4096) +
                        swz((uint32_t)(wr * 128 + wc * 16 + (p & 1) * 64));
        asm volatile("st.shared.v4.b32 [%0], {%1,%2,%3,%4};"
                     :: "r"(addr), "r"(v.x), "r"(v.y), "r"(v.z), "r"(v.w));
    }
}

// one 128-k stage for one warp: k-half kw (64 k elems = 4 k16 steps), m-half mw
__device__ __forceinline__ void mma_stage(uint32_t wb, int kw, int ksg_it,
                                          int mw, int lane,
                                          float acc[2][4][4]) {
    const int lrow = lane & 15;
    const uint32_t lk16 = (uint32_t)((lane >> 4) * 16);
    const uint32_t wbh = wb + (uint32_t)(kw * 4096);   // k-warp's half

#pragma unroll
    for (int ks = 0; ks < 4; ++ks) {
        const uint32_t kb = (uint32_t)(ks * 32) + lk16;
        uint32_t b[2][4];
#pragma unroll
        for (int h = 0; h < 2; ++h)
            ldm_x4(b[h][0], b[h][1], b[h][2], b[h][3],
                   wbh + swz((uint32_t)((h * 16 + lrow) * 128) + kb));
        const int ksg = ksg_it + kw * 4 + ks;
#pragma unroll
        for (int mt = 0; mt < 2; ++mt) {
            uint4 a = g_xf[(size_t)(ksg * 4 + mw * 2 + mt) * 32 + lane];
#pragma unroll
            for (int h = 0; h < 2; ++h) {
                mma_f16(acc[mt][h * 2 + 0], a, b[h][0], b[h][2]);
                mma_f16(acc[mt][h * 2 + 1], a, b[h][1], b[h][3]);
            }
        }
    }
}

__global__ __launch_bounds__(128, 4) void qlin(
    const float* __restrict__ wgt,
    const float* __restrict__ alpha,
    const float* __restrict__ bias,
    float* __restrict__ out)
{
    __shared__ __align__(1024) unsigned char smem[2 * STAGE_BYTES];  // 16KB
    __shared__ unsigned int s_last;

    const int otile  = blockIdx.x & (NTILES - 1);
    const int khalf  = blockIdx.x >> 8;
    const int n0     = otile * OTILE;
    const int k0     = khalf * KHALF;

    const int tid  = threadIdx.x;
    const int lane = tid & 31;
    const int warp = tid >> 5;
    const int kw = warp >> 1;          // k-half within stage
    const int mw = warp & 1;           // m-half (batch)

    const uint32_t smem_base = (uint32_t)__cvta_generic_to_shared(smem);

    // weight loader mapping: 4 threads per O-row (32 rows), 8-float chunks
    const int wr = tid >> 2;
    const int wc = tid & 3;
    const float thr = 0.5f * (alpha[n0 + wr] + 1e-8f);
    const float* wp0 = wgt + (size_t)(n0 + wr) * IOD + k0 + wc * 8;

    float acc[2][4][4];
#pragma unroll
    for (int i = 0; i < 2; ++i)
#pragma unroll
        for (int j = 0; j < 4; ++j)
#pragma unroll
            for (int k = 0; k < 4; ++k) acc[i][j][k] = 0.0f;

    uint4 wreg[8];

    // prologue: fill stage 0
    load_w(wp0, wreg);
    store_w(smem_base, 0, wr, wc, thr, wreg);
    __syncthreads();

    const int ksg0 = k0 / 16;
    for (int it = 0; it < NITER; ++it) {
        const int cur = it & 1;
        if (it + 1 < NITER)
            load_w(wp0 + (it + 1) * KC, wreg);

        mma_stage(smem_base + cur * STAGE_BYTES, kw, ksg0 + it * 8, mw, lane, acc);

        if (it + 1 < NITER)
            store_w(smem_base, cur ^ 1, wr, wc, thr, wreg);
        __syncthreads();
    }

    // ---- cross-k reduce: kw=1 warps dump acc to smem, kw=0 warps add ----
    float4* rbuf = reinterpret_cast<float4*>(smem);   // 8KB, aliases stages
    if (kw == 1) {
#pragma unroll
        for (int mt = 0; mt < 2; ++mt)
#pragma unroll
            for (int nt = 0; nt < 4; ++nt) {
                int r = mt * 4 + nt;
                rbuf[(mw * 8 + r) * 32 + lane] =
                    make_float4(acc[mt][nt][0], acc[mt][nt][1],
                                acc[mt][nt][2], acc[mt][nt][3]);
            }
    }
    __syncthreads();
    if (kw == 0) {
#pragma unroll
        for (int mt = 0; mt < 2; ++mt)
#pragma unroll
            for (int nt = 0; nt < 4; ++nt) {
                int r = mt * 4 + nt;
                float4 v = rbuf[(mw * 8 + r) * 32 + lane];
                acc[mt][nt][0] += v.x;
                acc[mt][nt][1] += v.y;
                acc[mt][nt][2] += v.z;
                acc[mt][nt][3] += v.w;
            }

        // scale by alpha in regs, write partial
        float* part = g_part[khalf];
#pragma unroll
        for (int mt = 0; mt < 2; ++mt) {
#pragma unroll
            for (int nt = 0; nt < 4; ++nt) {
                int brow = mw * 32 + mt * 16 + (lane >> 2);
                int o0   = n0 + nt * 8 + (lane & 3) * 2;
                float2 a2 = *reinterpret_cast<const float2*>(alpha + o0);
                acc[mt][nt][0] *= a2.x;
                acc[mt][nt][1] *= a2.y;
                acc[mt][nt][2] *= a2.x;
                acc[mt][nt][3] *= a2.y;
                float2 v0 = make_float2(acc[mt][nt][0], acc[mt][nt][1]);
                float2 v1 = make_float2(acc[mt][nt][2], acc[mt][nt][3]);
                *reinterpret_cast<float2*>(part + (size_t)brow * IOD + o0)       = v0;
                *reinterpret_cast<float2*>(part + (size_t)(brow + 8) * IOD + o0) = v1;
            }
        }
    }

    __threadfence();
    __syncthreads();
    if (tid == 0) {
        unsigned int old = atomicAdd(&g_cnt[otile], 1u);
        s_last = (((old + 1) % KSPLIT) == 0) ? 1u : 0u;
    }
    __syncthreads();

    if (s_last && kw == 0) {
        // this CTA finished second: its alpha*acc is in regs; add the other half + bias
        const float* other = g_part[khalf ^ 1];
#pragma unroll
        for (int mt = 0; mt < 2; ++mt) {
#pragma unroll
            for (int nt = 0; nt < 4; ++nt) {
                int brow = mw * 32 + mt * 16 + (lane >> 2);
                int o0   = n0 + nt * 8 + (lane & 3) * 2;
                float2 bi = *reinterpret_cast<const float2*>(bias + o0);
                float2 p0 = *reinterpret_cast<const float2*>(other + (size_t)brow * IOD + o0);
                float2 p1 = *reinterpret_cast<const float2*>(other + (size_t)(brow + 8) * IOD + o0);
                float2 v0, v1;
                v0.x = acc[mt][nt][0] + p0.x + bi.x;
                v0.y = acc[mt][nt][1] + p0.y + bi.y;
                v1.x = acc[mt][nt][2] + p1.x + bi.x;
                v1.y = acc[mt][nt][3] + p1.y + bi.y;
                *reinterpret_cast<float2*>(out + (size_t)brow * IOD + o0)       = v0;
                *reinterpret_cast<float2*>(out + (size_t)(brow + 8) * IOD + o0) = v1;
            }
        }
    }
}

extern "C" void kernel_launch(void* const* d_in, const int* in_sizes, int n_in,
                              void* d_out, int out_size) {
    const float* x     = (const float*)d_in[0];
    const float* wgt   = (const float*)d_in[1];
    const float* alpha = (const float*)d_in[2];
    const float* bias  = (const float*)d_in[3];
    float* out = (float*)d_out;

    prep_x<<<((IOD / 16) * 4 * 32 + 255) / 256, 256>>>(x);
    qlin<<<NTILES * KSPLIT, 128>>>(wgt, alpha, bias, out);
}